// round 17
// baseline (speedup 1.0000x reference)
#include <cuda_runtime.h>
#include <mma.h>
using namespace nvcuda;

#define NMAX 50000
#define EMAX 800000
#define DINC 128
#define HH 4
#define CC 32
#define ED 16
#define NEG 0.2f
#define LNEPS 1e-5f

// ---------------- scratch (static device globals; BSS-zeroed at load) -------
__device__ __align__(16) float g_h[(size_t)NMAX * DINC];     // 25.6 MB
__device__ __align__(16) float g_asrc[NMAX * HH];
__device__ __align__(16) float g_adst[NMAX * HH];
__device__ __align__(16) float g_ae[(size_t)EMAX * HH];      // 12.8 MB
__device__ __align__(16) float g_aesum[NMAX * HH];           // zero outside run
__device__ int   g_degi[NMAX];      // ALWAYS zero outside a run (k6 restores)
__device__ int   g_start[NMAX];
__device__ int   g_cursor[NMAX];
__device__ int   g_bsum[64];
__device__ __align__(8)  int2   g_sd[EMAX];                  // (src,dst)
__device__ int   g_csrc[EMAX];                               // CSR: src per slot
__device__ __align__(16) float4 g_cw[EMAX];                  // CSR: 4 head weights

// ---------------- K1a: index extraction + degree count (critical path) ------
__global__ void k1a_index(const void* __restrict__ ei, int E) {
    __shared__ int s_is64;
    int t = threadIdx.x;
    if (t == 0) s_is64 = 1;
    int e = blockIdx.x * 256 + t;
    __syncthreads();
    // dtype probe: int64 (<2^31) data has 0 in every odd int32 word of src[].
    if (e < E && ((const int*)ei)[2 * e + 1] != 0) s_is64 = 0;
    __syncthreads();
    if (e >= E) return;
    int src, dst;
    if (s_is64) {
        const long long* p = (const long long*)ei;
        src = (int)p[e];
        dst = (int)p[(size_t)E + e];
    } else {
        const int* p = (const int*)ei;
        src = p[e];
        dst = p[(size_t)E + e];
    }
    g_sd[e] = make_int2(src, dst);
    atomicAdd(&g_degi[dst], 1);
}

// ---------------- K1b: edge MLP -> a_e (independent of edge_index) ----------
__global__ void k1b_edge_mlp(const float* __restrict__ eattr,
                             const float* __restrict__ Wep,
                             const float* __restrict__ bep,
                             const float* __restrict__ W_edge,
                             const float* __restrict__ att_edge, int E) {
    __shared__ __align__(16) float sW[ED * ED];
    __shared__ __align__(16) float sb[ED];
    __shared__ __align__(16) float sv[ED * HH];
    int t = threadIdx.x;
    if (t < ED * ED) sW[t] = Wep[t];
    if (t < ED)      sb[t] = bep[t];
    if (t < ED * HH) {                      // per-block v = W_edge . att_edge
        int k = t >> 2, h = t & 3;
        float s = 0.f;
        #pragma unroll
        for (int c = 0; c < CC; c++)
            s += __ldg(&W_edge[k * (HH * CC) + h * CC + c]) *
                 __ldg(&att_edge[h * CC + c]);
        sv[k * HH + h] = s;
    }
    int e = blockIdx.x * 256 + t;
    __syncthreads();
    if (e >= E) return;

    const float4* ap = (const float4*)(eattr + (size_t)e * ED);
    float4 x0 = __ldg(ap + 0), x1 = __ldg(ap + 1);
    float4 x2 = __ldg(ap + 2), x3 = __ldg(ap + 3);
    float xin[ED] = {x0.x, x0.y, x0.z, x0.w, x1.x, x1.y, x1.z, x1.w,
                     x2.x, x2.y, x2.z, x2.w, x3.x, x3.y, x3.z, x3.w};

    const float4* sW4 = (const float4*)sW;
    const float4* sb4 = (const float4*)sb;
    const float4* sv4 = (const float4*)sv;
    float4 e0 = sb4[0], e1 = sb4[1], e2 = sb4[2], e3 = sb4[3];
    #pragma unroll
    for (int j = 0; j < ED; j++) {
        float a = xin[j];
        float4 w0 = sW4[j * 4 + 0];
        float4 w1 = sW4[j * 4 + 1];
        float4 w2 = sW4[j * 4 + 2];
        float4 w3 = sW4[j * 4 + 3];
        e0.x += a * w0.x; e0.y += a * w0.y; e0.z += a * w0.z; e0.w += a * w0.w;
        e1.x += a * w1.x; e1.y += a * w1.y; e1.z += a * w1.z; e1.w += a * w1.w;
        e2.x += a * w2.x; e2.y += a * w2.y; e2.z += a * w2.z; e2.w += a * w2.w;
        e3.x += a * w3.x; e3.y += a * w3.y; e3.z += a * w3.z; e3.w += a * w3.w;
    }
    float ea[ED] = {fmaxf(e0.x, 0.f), fmaxf(e0.y, 0.f), fmaxf(e0.z, 0.f),
                    fmaxf(e0.w, 0.f), fmaxf(e1.x, 0.f), fmaxf(e1.y, 0.f),
                    fmaxf(e1.z, 0.f), fmaxf(e1.w, 0.f), fmaxf(e2.x, 0.f),
                    fmaxf(e2.y, 0.f), fmaxf(e2.z, 0.f), fmaxf(e2.w, 0.f),
                    fmaxf(e3.x, 0.f), fmaxf(e3.y, 0.f), fmaxf(e3.z, 0.f),
                    fmaxf(e3.w, 0.f)};
    float4 ae = make_float4(0.f, 0.f, 0.f, 0.f);
    #pragma unroll
    for (int k = 0; k < ED; k++) {
        float a = ea[k];
        float4 vk = sv4[k];
        ae.x += a * vk.x; ae.y += a * vk.y;
        ae.z += a * vk.z; ae.w += a * vk.w;
    }
    *(float4*)&g_ae[(size_t)e * 4] = ae;
}

// ---------------- kscan1: per-block sums of degrees (coalesced) --------------
__global__ void kscan1(int N) {
    __shared__ int swarp[32];
    int t = threadIdx.x, lane = t & 31, wid = t >> 5;
    int i = blockIdx.x * 1024 + t;
    int v = (i < N) ? g_degi[i] : 0;
    #pragma unroll
    for (int o = 16; o > 0; o >>= 1) v += __shfl_xor_sync(0xffffffffu, v, o);
    if (lane == 0) swarp[wid] = v;
    __syncthreads();
    if (wid == 0) {
        int s = swarp[lane];
        #pragma unroll
        for (int o = 16; o > 0; o >>= 1) s += __shfl_xor_sync(0xffffffffu, s, o);
        if (lane == 0) g_bsum[blockIdx.x] = s;
    }
}

// ---------------- kscan2: block-local exclusive scan + bsum offset -----------
__global__ void kscan2(int N) {
    __shared__ int swarp[32];
    __shared__ int soff;
    int b = blockIdx.x, t = threadIdx.x, lane = t & 31, wid = t >> 5;

    if (wid == 0) {
        int s = 0;
        for (int j = lane; j < b; j += 32) s += g_bsum[j];
        #pragma unroll
        for (int o = 16; o > 0; o >>= 1) s += __shfl_xor_sync(0xffffffffu, s, o);
        if (lane == 0) soff = s;
    }

    int i = b * 1024 + t;
    int v = (i < N) ? g_degi[i] : 0;
    int incl = v;
    #pragma unroll
    for (int o = 1; o < 32; o <<= 1) {
        int u = __shfl_up_sync(0xffffffffu, incl, o);
        if (lane >= o) incl += u;
    }
    if (lane == 31) swarp[wid] = incl;
    __syncthreads();
    if (wid == 0) {
        int wv = swarp[lane];
        int winc = wv;
        #pragma unroll
        for (int o = 1; o < 32; o <<= 1) {
            int u = __shfl_up_sync(0xffffffffu, winc, o);
            if (lane >= o) winc += u;
        }
        swarp[lane] = winc - wv;   // exclusive prefix of warp sums
    }
    __syncthreads();
    if (i < N) {
        int e = soff + swarp[wid] + incl - v;
        g_start[i]  = e;
        g_cursor[i] = e;
    }
}

// ---------------- kfill_w: CSR fill WITH precomputed softmax weights --------
// Per edge: w4 = exp(leakyrelu(asrc[src] + adst[dst] + a_e[e])) for 4 heads,
// stored CSR-ordered. Also accumulates sum of a_e per dst (self-loop mean).
__global__ void kfill_w(int E) {
    int e = blockIdx.x * blockDim.x + threadIdx.x;
    if (e >= E) return;
    int2 sd = g_sd[e];
    float4 as = __ldg((const float4*)&g_asrc[(size_t)sd.x * 4]);
    float4 ad = __ldg((const float4*)&g_adst[(size_t)sd.y * 4]);
    float4 ae = *(const float4*)&g_ae[(size_t)e * 4];
    float a0 = as.x + ad.x + ae.x, a1 = as.y + ad.y + ae.y;
    float a2 = as.z + ad.z + ae.z, a3 = as.w + ad.w + ae.w;
    a0 = (a0 >= 0.f) ? a0 : NEG * a0;  a1 = (a1 >= 0.f) ? a1 : NEG * a1;
    a2 = (a2 >= 0.f) ? a2 : NEG * a2;  a3 = (a3 >= 0.f) ? a3 : NEG * a3;
    int pos = atomicAdd(&g_cursor[sd.y], 1);
    g_csrc[pos] = sd.x;
    g_cw[pos] = make_float4(__expf(a0), __expf(a1), __expf(a2), __expf(a3));
    asm volatile("red.global.add.v4.f32 [%0], {%1,%2,%3,%4};" ::
                 "l"(&g_aesum[(size_t)sd.y * 4]),
                 "f"(ae.x), "f"(ae.y), "f"(ae.z), "f"(ae.w) : "memory");
}

// ---------------- K2: h = x@W_lin via TF32 wmma ------------------------------
__global__ void k2_wmma(const float* __restrict__ x,
                        const float* __restrict__ Wlin, int N) {
    __shared__ __align__(16) float sW[DINC * DINC];   // 64 KB
    int t = threadIdx.x;
    for (int i = t; i < DINC * DINC / 4; i += 256)
        ((float4*)sW)[i] = __ldg(&((const float4*)Wlin)[i]);
    __syncthreads();

    int w = t >> 5;
    int row0 = blockIdx.x * 128 + w * 16;
    if (row0 >= N || row0 + 16 > N) return;

    wmma::fragment<wmma::accumulator, 16, 16, 8, float> c[8];
    #pragma unroll
    for (int i = 0; i < 8; i++) wmma::fill_fragment(c[i], 0.f);

    #pragma unroll 4
    for (int k0 = 0; k0 < DINC; k0 += 8) {
        wmma::fragment<wmma::matrix_a, 16, 16, 8,
                       wmma::precision::tf32, wmma::row_major> a;
        wmma::load_matrix_sync(a, x + (size_t)row0 * DINC + k0, DINC);
        #pragma unroll
        for (int i = 0; i < a.num_elements; i++)
            a.x[i] = wmma::__float_to_tf32(a.x[i]);
        #pragma unroll
        for (int nt = 0; nt < 8; nt++) {
            wmma::fragment<wmma::matrix_b, 16, 16, 8,
                           wmma::precision::tf32, wmma::row_major> b;
            wmma::load_matrix_sync(b, sW + k0 * DINC + nt * 16, DINC);
            #pragma unroll
            for (int i = 0; i < b.num_elements; i++)
                b.x[i] = wmma::__float_to_tf32(b.x[i]);
            wmma::mma_sync(c[nt], a, b, c[nt]);
        }
    }
    #pragma unroll
    for (int nt = 0; nt < 8; nt++)
        wmma::store_matrix_sync(g_h + (size_t)row0 * DINC + nt * 16, c[nt],
                                DINC, wmma::mem_row_major);
}

// ---------------- K2b: a_src / a_dst from g_h (warp per node) ----------------
__global__ void k2b_attn(const float* __restrict__ att_src,
                         const float* __restrict__ att_dst, int N) {
    int n = (int)((blockIdx.x * (size_t)blockDim.x + threadIdx.x) >> 5);
    int lane = threadIdx.x & 31;
    if (n >= N) return;
    float4 a_s = __ldg((const float4*)&att_src[lane * 4]);
    float4 a_d = __ldg((const float4*)&att_dst[lane * 4]);
    float4 hv = *(const float4*)&g_h[(size_t)n * DINC + lane * 4];
    float ps = hv.x * a_s.x + hv.y * a_s.y + hv.z * a_s.z + hv.w * a_s.w;
    float pd = hv.x * a_d.x + hv.y * a_d.y + hv.z * a_d.z + hv.w * a_d.w;
    #pragma unroll
    for (int o = 1; o < 8; o <<= 1) {
        ps += __shfl_xor_sync(0xffffffffu, ps, o);
        pd += __shfl_xor_sync(0xffffffffu, pd, o);
    }
    if ((lane & 7) == 0) {
        int head = lane >> 3;
        g_asrc[n * HH + head] = ps;
        g_adst[n * HH + head] = pd;
    }
}

// ---------------- K6: pure streaming gather + self-loop + LN -----------------
// One warp per node; lane owns 4 channels (float4 at lane*4), head = lane>>3.
// Weights already in g_cw (CSR-ordered) — no smem, no syncwarp, no exp loop.
__global__ void k6_gather(float* __restrict__ out, const float* __restrict__ x,
                          const float* __restrict__ bias,
                          const float* __restrict__ lng,
                          const float* __restrict__ lnb, int N) {
    int n = (int)((blockIdx.x * (size_t)blockDim.x + threadIdx.x) >> 5);
    int lane = threadIdx.x & 31;
    if (n >= N) return;
    int head = lane >> 3;

    int deg   = g_degi[n];
    int start = g_start[n];

    float4 acc = make_float4(0.f, 0.f, 0.f, 0.f);
    float  den = 0.f;

    int p = 0;
    for (; p + 4 <= deg; p += 4) {
        int s0 = __ldg(&g_csrc[start + p + 0]);
        int s1 = __ldg(&g_csrc[start + p + 1]);
        int s2 = __ldg(&g_csrc[start + p + 2]);
        int s3 = __ldg(&g_csrc[start + p + 3]);
        float4 w0 = __ldg(&g_cw[start + p + 0]);
        float4 w1 = __ldg(&g_cw[start + p + 1]);
        float4 w2 = __ldg(&g_cw[start + p + 2]);
        float4 w3 = __ldg(&g_cw[start + p + 3]);
        float4 hv0 = __ldg((const float4*)&g_h[(size_t)s0 * DINC + lane * 4]);
        float4 hv1 = __ldg((const float4*)&g_h[(size_t)s1 * DINC + lane * 4]);
        float4 hv2 = __ldg((const float4*)&g_h[(size_t)s2 * DINC + lane * 4]);
        float4 hv3 = __ldg((const float4*)&g_h[(size_t)s3 * DINC + lane * 4]);
        float g0 = (head & 2) ? ((head & 1) ? w0.w : w0.z)
                              : ((head & 1) ? w0.y : w0.x);
        float g1 = (head & 2) ? ((head & 1) ? w1.w : w1.z)
                              : ((head & 1) ? w1.y : w1.x);
        float g2 = (head & 2) ? ((head & 1) ? w2.w : w2.z)
                              : ((head & 1) ? w2.y : w2.x);
        float g3 = (head & 2) ? ((head & 1) ? w3.w : w3.z)
                              : ((head & 1) ? w3.y : w3.x);
        acc.x += g0 * hv0.x; acc.y += g0 * hv0.y;
        acc.z += g0 * hv0.z; acc.w += g0 * hv0.w; den += g0;
        acc.x += g1 * hv1.x; acc.y += g1 * hv1.y;
        acc.z += g1 * hv1.z; acc.w += g1 * hv1.w; den += g1;
        acc.x += g2 * hv2.x; acc.y += g2 * hv2.y;
        acc.z += g2 * hv2.z; acc.w += g2 * hv2.w; den += g2;
        acc.x += g3 * hv3.x; acc.y += g3 * hv3.y;
        acc.z += g3 * hv3.z; acc.w += g3 * hv3.w; den += g3;
    }
    for (; p < deg; p++) {
        int s0 = __ldg(&g_csrc[start + p]);
        float4 w0 = __ldg(&g_cw[start + p]);
        float4 hv = __ldg((const float4*)&g_h[(size_t)s0 * DINC + lane * 4]);
        float g0 = (head & 2) ? ((head & 1) ? w0.w : w0.z)
                              : ((head & 1) ? w0.y : w0.x);
        acc.x += g0 * hv.x; acc.y += g0 * hv.y;
        acc.z += g0 * hv.z; acc.w += g0 * hv.w; den += g0;
    }

    // ---- self-loop: ael = mean of incoming a_e (accumulated in kfill_w) ----
    float4 aes4 = *(const float4*)&g_aesum[(size_t)n * 4];
    float4 as4  = __ldg((const float4*)&g_asrc[(size_t)n * 4]);
    float4 ad4  = __ldg((const float4*)&g_adst[(size_t)n * 4]);
    float aes = (head & 2) ? ((head & 1) ? aes4.w : aes4.z)
                           : ((head & 1) ? aes4.y : aes4.x);
    float asl = (head & 2) ? ((head & 1) ? as4.w : as4.z)
                           : ((head & 1) ? as4.y : as4.x);
    float adl = (head & 2) ? ((head & 1) ? ad4.w : ad4.z)
                           : ((head & 1) ? ad4.y : ad4.x);
    float al = asl + adl + aes / (float)max(deg, 1);
    al = (al >= 0.f) ? al : NEG * al;
    float ex = __expf(al);
    float4 hn = *(const float4*)&g_h[(size_t)n * DINC + lane * 4];
    acc.x += ex * hn.x; acc.y += ex * hn.y;
    acc.z += ex * hn.z; acc.w += ex * hn.w;
    den += ex;

    float rd = 1.f / den;
    float4 b4 = __ldg((const float4*)&bias[lane * 4]);
    float4 x4 = __ldg((const float4*)&x[(size_t)n * DINC + lane * 4]);
    float4 v = make_float4(acc.x * rd + b4.x + x4.x, acc.y * rd + b4.y + x4.y,
                           acc.z * rd + b4.z + x4.z, acc.w * rd + b4.w + x4.w);

    // ---- LayerNorm over 128 channels (warp reduce) ----
    float s  = v.x + v.y + v.z + v.w;
    float s2 = v.x * v.x + v.y * v.y + v.z * v.z + v.w * v.w;
    #pragma unroll
    for (int o = 16; o > 0; o >>= 1) {
        s  += __shfl_xor_sync(0xffffffffu, s, o);
        s2 += __shfl_xor_sync(0xffffffffu, s2, o);
    }
    float mu  = s * (1.f / 128.f);
    float var = s2 * (1.f / 128.f) - mu * mu;
    float r = rsqrtf(var + LNEPS);
    float4 g4 = __ldg((const float4*)&lng[lane * 4]);
    float4 o4 = __ldg((const float4*)&lnb[lane * 4]);
    float4 res = make_float4((v.x - mu) * r * g4.x + o4.x,
                             (v.y - mu) * r * g4.y + o4.y,
                             (v.z - mu) * r * g4.z + o4.z,
                             (v.w - mu) * r * g4.w + o4.w);
    *(float4*)&out[(size_t)n * DINC + lane * 4] = res;

    // restore zero-invariants for the next graph replay
    if (lane == 0) {
        g_degi[n] = 0;
        *(float4*)&g_aesum[(size_t)n * 4] = make_float4(0.f, 0.f, 0.f, 0.f);
    }
}

// ---------------- launch: 3-way overlap, join at kfill_w ---------------------
// stream0: k1a -> scan -> (wait s2,s3) -> kfill_w -> k6
// s2:      k2_wmma -> k2b         s3: k1b
extern "C" void kernel_launch(void* const* d_in, const int* in_sizes, int n_in,
                              void* d_out, int out_size) {
    const float* x        = (const float*)d_in[0];
    const void*  ei       = (const void*)d_in[1];
    const float* eattr    = (const float*)d_in[2];
    const float* Wep      = (const float*)d_in[3];
    const float* bep      = (const float*)d_in[4];
    const float* Wlin     = (const float*)d_in[5];
    const float* Wedge    = (const float*)d_in[6];
    const float* att_src  = (const float*)d_in[7];
    const float* att_dst  = (const float*)d_in[8];
    const float* att_edge = (const float*)d_in[9];
    const float* bias     = (const float*)d_in[10];
    const float* lng      = (const float*)d_in[11];
    const float* lnb      = (const float*)d_in[12];
    float* out = (float*)d_out;

    int N = in_sizes[0] / DINC;
    int E = in_sizes[2] / ED;
    int nscan = (N + 1023) / 1024;

    static cudaStream_t s2 = nullptr, s3 = nullptr;
    static cudaEvent_t evFork = nullptr, evJoin2 = nullptr, evJoin3 = nullptr;
    if (s2 == nullptr) {
        cudaStreamCreateWithFlags(&s2, cudaStreamNonBlocking);
        cudaStreamCreateWithFlags(&s3, cudaStreamNonBlocking);
        cudaEventCreateWithFlags(&evFork, cudaEventDisableTiming);
        cudaEventCreateWithFlags(&evJoin2, cudaEventDisableTiming);
        cudaEventCreateWithFlags(&evJoin3, cudaEventDisableTiming);
    }

    cudaEventRecord(evFork, 0);
    cudaStreamWaitEvent(s2, evFork, 0);
    cudaStreamWaitEvent(s3, evFork, 0);

    // idx0: stream0 head
    k1a_index<<<(E + 255) / 256, 256>>>(ei, E);
    // idx1-2: s2 GEMM branch
    k2_wmma<<<(N + 127) / 128, 256, 0, s2>>>(x, Wlin, N);
    k2b_attn<<<(N + 7) / 8, 256, 0, s2>>>(att_src, att_dst, N);
    cudaEventRecord(evJoin2, s2);
    // idx3: s3 edge MLP (ncu capture slot — measure under contention)
    k1b_edge_mlp<<<(E + 255) / 256, 256, 0, s3>>>(eattr, Wep, bep,
                                                  Wedge, att_edge, E);
    cudaEventRecord(evJoin3, s3);
    // idx4-5: scans on stream0
    kscan1<<<nscan, 1024>>>(N);
    kscan2<<<nscan, 1024>>>(N);

    // global join: kfill_w needs a_e (s3) and asrc/adst (s2)
    cudaStreamWaitEvent(0, evJoin2, 0);
    cudaStreamWaitEvent(0, evJoin3, 0);
    kfill_w<<<(E + 255) / 256, 256>>>(E);
    k6_gather<<<(N + 7) / 8, 256>>>(out, x, bias, lng, lnb, N);
}